// round 13
// baseline (speedup 1.0000x reference)
#include <cuda_runtime.h>
#include <cuda_bf16.h>
#include <cstdint>

#define IMG 96
#define CH 96
#define NB 16
#define NPIX (IMG*IMG)           // 9216
#define PPIX (98*98)             // 9604 padded pixels (1-halo)
#define KTOT 864                 // 9 taps * 96 ci, = 27*32 exactly
#define NCHUNK 27                // K chunks of 32
#define NTILE 128                // pixels per GEMM tile
#define TILES_PER_B 72
#define ROWB 80                  // smem row stride bytes (64B data + 16B pad)
#define ROWA 144                 // attn smem row stride (128B data + 16B pad)

typedef __nv_bfloat16 bf16;

// ---------------- device scratch (BSS => zero; halo rows never written => stay 0) ----
__device__ __align__(128) bf16 g_xTh[(size_t)NB*PPIX*CH];   // transposed padded input hi (x, later y3)
__device__ __align__(128) bf16 g_xTl[(size_t)NB*PPIX*CH];   // lo
__device__ __align__(128) bf16 g_Wh[(size_t)3*CH*KTOT];     // weights, K order tap*96+ci
__device__ __align__(128) bf16 g_Wl[(size_t)3*CH*KTOT];
__device__ __align__(128) bf16 g_Snh[(size_t)NB*CH*KTOT];   // softmaxed attn weights hi
__device__ __align__(128) bf16 g_Snl[(size_t)NB*CH*KTOT];
__device__ float g_u1[(size_t)NB*CH*9*1024];   // unfolded conv1 out (f32)
__device__ float g_u2[(size_t)NB*CH*9*1024];   // unfolded conv2 out (f32)
__device__ __align__(128) bf16 g_u1h[(size_t)NB*CH*9*1024]; // bf16 hi/lo copies for attn mma
__device__ __align__(128) bf16 g_u1l[(size_t)NB*CH*9*1024];
__device__ __align__(128) bf16 g_u2h[(size_t)NB*CH*9*1024];
__device__ __align__(128) bf16 g_u2l[(size_t)NB*CH*9*1024];
__device__ float g_y3[(size_t)NB*CH*NPIX];     // conv3 out NCHW
__device__ float g_S [(size_t)NB*CH*KTOT];     // attn logits

// ---------------- helpers ----------------
__device__ __forceinline__ uint32_t smem_u32(const void* p) {
    uint32_t a;
    asm("{ .reg .u64 t; cvta.to.shared.u64 t, %1; cvt.u32.u64 %0, t; }" : "=r"(a) : "l"(p));
    return a;
}
__device__ __forceinline__ void cp_async16(uint32_t dst, const void* src) {
    asm volatile("cp.async.cg.shared.global [%0], [%1], 16;" :: "r"(dst), "l"(src));
}
__device__ __forceinline__ void cp_commit() { asm volatile("cp.async.commit_group;" ::: "memory"); }
template<int N>
__device__ __forceinline__ void cp_wait() { asm volatile("cp.async.wait_group %0;" :: "n"(N) : "memory"); }

__device__ __forceinline__ void ldsm_x4(uint32_t* r, uint32_t addr) {
    asm volatile("ldmatrix.sync.aligned.m8n8.x4.shared.b16 {%0,%1,%2,%3}, [%4];"
                 : "=r"(r[0]), "=r"(r[1]), "=r"(r[2]), "=r"(r[3]) : "r"(addr));
}
__device__ __forceinline__ void ldsm_x2(uint32_t* r, uint32_t addr) {
    asm volatile("ldmatrix.sync.aligned.m8n8.x2.shared.b16 {%0,%1}, [%2];"
                 : "=r"(r[0]), "=r"(r[1]) : "r"(addr));
}
__device__ __forceinline__ void mma_bf16(float* d, const uint32_t* a, const uint32_t* b) {
    asm volatile("mma.sync.aligned.m16n8k16.row.col.f32.bf16.bf16.f32 "
                 "{%0,%1,%2,%3}, {%4,%5,%6,%7}, {%8,%9}, {%0,%1,%2,%3};"
                 : "+f"(d[0]), "+f"(d[1]), "+f"(d[2]), "+f"(d[3])
                 : "r"(a[0]), "r"(a[1]), "r"(a[2]), "r"(a[3]), "r"(b[0]), "r"(b[1]));
}
__device__ __forceinline__ uint32_t pack2(bf16 a, bf16 b) {
    __nv_bfloat162 t(a, b);
    return *reinterpret_cast<uint32_t*>(&t);
}

// ---------------------------------------------------------------------------
// prepT: src NCHW fp32 -> transposed padded [b][(h+1)*98+(w+1)][ci] bf16 hi/lo.
// ---------------------------------------------------------------------------
__global__ __launch_bounds__(256)
void prepT_kernel(const float* __restrict__ src,
                  bf16* __restrict__ dhi, bf16* __restrict__ dlo)
{
    __shared__ float s[CH][97];
    const int h = blockIdx.x, b = blockIdx.y, tid = threadIdx.x;

    for (int e = tid; e < CH*IMG; e += 256) {
        int ci = e / IMG, w = e - ci*IMG;
        s[ci][w] = src[(((size_t)b*CH + ci)*IMG + h)*IMG + w];
    }
    __syncthreads();

    for (int e = tid; e < IMG*12; e += 256) {
        int w = e / 12, seg = e - w*12;
        int ci0 = seg*8;
        uint32_t uh[4], ul[4];
        #pragma unroll
        for (int i2 = 0; i2 < 4; i2++) {
            float a = s[ci0 + i2*2][w], c2 = s[ci0 + i2*2 + 1][w];
            bf16 ha = __float2bfloat16(a), hc = __float2bfloat16(c2);
            bf16 la = __float2bfloat16(a - __bfloat162float(ha));
            bf16 lc = __float2bfloat16(c2 - __bfloat162float(hc));
            uh[i2] = pack2(ha, hc);
            ul[i2] = pack2(la, lc);
        }
        size_t base = ((size_t)b*PPIX + (size_t)(h+1)*98 + (w+1))*CH + ci0;
        *reinterpret_cast<uint4*>(dhi + base) = make_uint4(uh[0],uh[1],uh[2],uh[3]);
        *reinterpret_cast<uint4*>(dlo + base) = make_uint4(ul[0],ul[1],ul[2],ul[3]);
    }
}

// ---------------------------------------------------------------------------
__global__ __launch_bounds__(256)
void prep_w_kernel(const float* __restrict__ W1, const float* __restrict__ W2,
                   const float* __restrict__ W3)
{
    int idx = blockIdx.x*256 + threadIdx.x;
    if (idx >= 3*CH*KTOT) return;
    int conv = idx / (CH*KTOT);
    int r = idx - conv*(CH*KTOT);
    int co = r / KTOT, k = r - co*KTOT;
    int tap = k / CH, ci = k - tap*CH;
    const float* W = (conv == 0) ? W1 : (conv == 1) ? W2 : W3;
    float v = W[((size_t)co*CH + ci)*9 + tap];
    bf16 hi = __float2bfloat16(v);
    g_Wh[idx] = hi;
    g_Wl[idx] = __float2bfloat16(v - __bfloat162float(hi));
}

// ---------------------------------------------------------------------------
// convert_u: fp32 unfold buffers -> bf16 hi/lo (coalesced, vectorized)
// ---------------------------------------------------------------------------
__global__ __launch_bounds__(256)
void convert_u_kernel(const float* __restrict__ u1, const float* __restrict__ u2,
                      bf16* __restrict__ u1h, bf16* __restrict__ u1l,
                      bf16* __restrict__ u2h, bf16* __restrict__ u2l)
{
    const size_t n4 = (size_t)NB*CH*9*1024/4;
    size_t i = (size_t)blockIdx.x*256 + threadIdx.x;
    if (i >= n4) return;
    float4 a = reinterpret_cast<const float4*>(u1)[i];
    float4 b = reinterpret_cast<const float4*>(u2)[i];
    bf16 h0=__float2bfloat16(a.x), h1=__float2bfloat16(a.y),
         h2=__float2bfloat16(a.z), h3=__float2bfloat16(a.w);
    reinterpret_cast<uint2*>(u1h)[i] =
        make_uint2(pack2(h0,h1), pack2(h2,h3));
    reinterpret_cast<uint2*>(u1l)[i] =
        make_uint2(pack2(__float2bfloat16(a.x-__bfloat162float(h0)),
                         __float2bfloat16(a.y-__bfloat162float(h1))),
                   pack2(__float2bfloat16(a.z-__bfloat162float(h2)),
                         __float2bfloat16(a.w-__bfloat162float(h3))));
    bf16 g0=__float2bfloat16(b.x), g1=__float2bfloat16(b.y),
         g2=__float2bfloat16(b.z), g3=__float2bfloat16(b.w);
    reinterpret_cast<uint2*>(u2h)[i] =
        make_uint2(pack2(g0,g1), pack2(g2,g3));
    reinterpret_cast<uint2*>(u2l)[i] =
        make_uint2(pack2(__float2bfloat16(b.x-__bfloat162float(g0)),
                         __float2bfloat16(b.y-__bfloat162float(g1))),
                   pack2(__float2bfloat16(b.z-__bfloat162float(g2)),
                         __float2bfloat16(b.w-__bfloat162float(g3))));
}

// ---------------------------------------------------------------------------
// gemm_conv1: single-conv GEMM, 2 CTAs/SM (16 warps) to overlap barriers.
// D[co][p] = sum_k A[co][k]*B[p][k], hi/lo 3-term bf16 mma, 3-stage pipeline.
// MODE 0: unfold layout f32 -> o0.  MODE 1: NCHW f32 -> o0 (per-batch A).
// ---------------------------------------------------------------------------
template<int MODE>
__global__ __launch_bounds__(256, 2)
void gemm_conv1(const bf16* __restrict__ Bh_, const bf16* __restrict__ Bl_,
                const bf16* __restrict__ Ah_, const bf16* __restrict__ Al_,
                long aStride, float* __restrict__ o0)
{
    extern __shared__ __align__(1024) char smem[];
    constexpr int AOFF  = 2*NTILE*ROWB;          // 20480
    constexpr int ABUF  = 96*ROWB;               // 7680
    constexpr int STAGE = AOFF + 2*ABUF;         // 35840

    const int tid = threadIdx.x, wid = tid >> 5, lane = tid & 31;
    const int wm = wid & 1, wn = wid >> 1;
    const int ntile = blockIdx.x, b = blockIdx.y;
    const uint32_t sb = smem_u32(smem);

    const int r0 = tid >> 2, seg0 = tid & 3;
    const int q0 = ntile*NTILE + r0;
    const int pb0 = (q0/IMG)*98 + (q0 - (q0/IMG)*IMG);
    const int q1 = q0 + 64;
    const int pb1 = (q1/IMG)*98 + (q1 - (q1/IMG)*IMG);

    const bf16* Bs[2] = { Bh_ + (size_t)b*PPIX*CH, Bl_ + (size_t)b*PPIX*CH };
    const bf16* As[2] = { Ah_ + (size_t)b*aStride, Al_ + (size_t)b*aStride };

    float acc[3][4][4];
    #pragma unroll
    for (int mt = 0; mt < 3; mt++)
        #pragma unroll
        for (int nt = 0; nt < 4; nt++)
            #pragma unroll
            for (int j = 0; j < 4; j++) acc[mt][nt][j] = 0.f;

    auto load_chunk = [&](int chunk, int stage) {
        const int tap = chunk/3;
        const int ci0 = (chunk - tap*3)*32;
        const int dh = tap/3, dw = tap - dh*3;
        const int doff = dh*98 + dw;
        const int koff = tap*CH + ci0;
        const uint32_t base = sb + stage*STAGE;
        #pragma unroll
        for (int t = 0; t < 2; t++) {
            cp_async16(base + t*(NTILE*ROWB) + r0*ROWB + seg0*16,
                       Bs[t] + (size_t)(pb0 + doff)*CH + ci0 + seg0*8);
            cp_async16(base + t*(NTILE*ROWB) + (r0+64)*ROWB + seg0*16,
                       Bs[t] + (size_t)(pb1 + doff)*CH + ci0 + seg0*8);
        }
        #pragma unroll
        for (int hl = 0; hl < 2; hl++) {
            const bf16* src = As[hl] + koff;
            uint32_t abase = base + AOFF + hl*ABUF;
            cp_async16(abase + r0*ROWB + seg0*16, src + (size_t)r0*KTOT + seg0*8);
            if (tid < 128)
                cp_async16(abase + (r0+64)*ROWB + seg0*16,
                           src + (size_t)(r0+64)*KTOT + seg0*8);
        }
        cp_commit();
    };

    load_chunk(0, 0);
    load_chunk(1, 1);

    for (int c = 0; c < NCHUNK; c++) {
        if (c + 2 < NCHUNK) { load_chunk(c+2, (c+2)%3); cp_wait<2>(); }
        else if (c + 1 < NCHUNK) { cp_wait<1>(); }
        else { cp_wait<0>(); }
        __syncthreads();

        const uint32_t base = sb + (c % 3)*STAGE;
        #pragma unroll
        for (int ks = 0; ks < 2; ks++) {
            uint32_t bh[4][2], bl[4][2];
            #pragma unroll
            for (int nt = 0; nt < 4; nt++) {
                int rr = lane & 7, ii = (lane >> 3) & 1;
                int nl = wn*32 + nt*8 + rr;
                uint32_t ad = base + nl*ROWB + (ks*2 + ii)*16;
                ldsm_x2(bh[nt], ad);
                ldsm_x2(bl[nt], ad + NTILE*ROWB);
            }
            uint32_t ah[3][4], al[3][4];
            #pragma unroll
            for (int mt = 0; mt < 3; mt++) {
                int ii = lane >> 3, rr = lane & 7;
                int ml = wm*48 + mt*16 + (ii & 1)*8 + rr;
                uint32_t ad = base + AOFF + ml*ROWB + (ks*2 + (ii >> 1))*16;
                ldsm_x4(ah[mt], ad);
                ldsm_x4(al[mt], ad + ABUF);
            }
            #pragma unroll
            for (int mt = 0; mt < 3; mt++)
                #pragma unroll
                for (int nt = 0; nt < 4; nt++) {
                    mma_bf16(acc[mt][nt], ah[mt], bh[nt]);
                    mma_bf16(acc[mt][nt], ah[mt], bl[nt]);
                    mma_bf16(acc[mt][nt], al[mt], bh[nt]);
                }
        }
        __syncthreads();
    }

    // ---- epilogue ----
    #pragma unroll
    for (int mt = 0; mt < 3; mt++) {
        #pragma unroll
        for (int nt = 0; nt < 4; nt++) {
            int co0 = wm*48 + mt*16 + (lane >> 2);
            int p0  = ntile*NTILE + wn*32 + nt*8 + (lane & 3)*2;
            #pragma unroll
            for (int half = 0; half < 2; half++) {
                int co = co0 + half*8;
                float v0 = acc[mt][nt][half*2 + 0];
                float v1 = acc[mt][nt][half*2 + 1];
                if (MODE == 0) {
                    size_t obase = ((size_t)b*CH + co)*9*1024;
                    int h0 = p0 / IMG, w0 = p0 - h0*IMG;
                    o0[obase + (size_t)((h0%3)*3 + (w0%3))*1024 + (h0/3)*32 + (w0/3)] = v0;
                    int p1 = p0 + 1;
                    int h1 = p1 / IMG, w1 = p1 - h1*IMG;
                    o0[obase + (size_t)((h1%3)*3 + (w1%3))*1024 + (h1/3)*32 + (w1/3)] = v1;
                } else {
                    size_t o = ((size_t)b*CH + co)*NPIX + p0;
                    o0[o]     = v0;
                    o0[o + 1] = v1;
                }
            }
        }
    }
}

// ---------------------------------------------------------------------------
// attn_mma: S[b][d][c*9+k] = sum_l u1[b,c,k,l]*u2[b,d,k,l], 3-term bf16 mma.
// One block per (k, b): M=96 (c), N=96 (d), K=1024 in 16 chunks of 64.
// ---------------------------------------------------------------------------
__global__ __launch_bounds__(256, 1)
void attn_mma_kernel(const bf16* __restrict__ u1h, const bf16* __restrict__ u1l,
                     const bf16* __restrict__ u2h, const bf16* __restrict__ u2l,
                     float* __restrict__ S)
{
    extern __shared__ __align__(1024) char smem[];
    constexpr int TILE  = 96*ROWA;     // 13824
    constexpr int STG   = 4*TILE;      // 55296
    constexpr int NCH   = 16;

    const int kk = blockIdx.x, b = blockIdx.y;
    const int tid = threadIdx.x, wid = tid >> 5, lane = tid & 31;
    const int wm = wid & 1, wn = wid >> 1;
    const uint32_t sb = smem_u32(smem);

    const size_t rbase = ((size_t)b*CH*9 + kk)*1024;
    const bf16* srcs[4] = { u1h + rbase, u1l + rbase, u2h + rbase, u2l + rbase };

    float acc[3][3][4];
    #pragma unroll
    for (int mt = 0; mt < 3; mt++)
        #pragma unroll
        for (int nt = 0; nt < 3; nt++)
            #pragma unroll
            for (int j = 0; j < 4; j++) acc[mt][nt][j] = 0.f;

    auto load_chunk = [&](int chunk, int stage) {
        const uint32_t base = sb + stage*STG;
        #pragma unroll
        for (int t = 0; t < 4; t++) {
            for (int e = tid; e < 96*8; e += 256) {
                int row = e >> 3, seg = e & 7;
                cp_async16(base + t*TILE + row*ROWA + seg*16,
                           srcs[t] + (size_t)row*9216 + chunk*64 + seg*8);
            }
        }
        cp_commit();
    };

    load_chunk(0, 0);
    load_chunk(1, 1);

    for (int c = 0; c < NCH; c++) {
        if (c + 2 < NCH) { load_chunk(c+2, (c+2)%3); cp_wait<2>(); }
        else if (c + 1 < NCH) { cp_wait<1>(); }
        else { cp_wait<0>(); }
        __syncthreads();

        const uint32_t base = sb + (c % 3)*STG;
        #pragma unroll
        for (int ks = 0; ks < 4; ks++) {
            uint32_t bh[3][2], bl[3][2];
            #pragma unroll
            for (int nt = 0; nt < 3; nt++) {
                int rr = lane & 7, ii = (lane >> 3) & 1;
                int nl = wn*24 + nt*8 + rr;
                uint32_t ad = base + 2*TILE + nl*ROWA + (ks*2 + ii)*16;
                ldsm_x2(bh[nt], ad);
                ldsm_x2(bl[nt], ad + TILE);
            }
            uint32_t ah[3][4], al[3][4];
            #pragma unroll
            for (int mt = 0; mt < 3; mt++) {
                int ii = lane >> 3, rr = lane & 7;
                int ml = wm*48 + mt*16 + (ii & 1)*8 + rr;
                uint32_t ad = base + ml*ROWA + (ks*2 + (ii >> 1))*16;
                ldsm_x4(ah[mt], ad);
                ldsm_x4(al[mt], ad + TILE);
            }
            #pragma unroll
            for (int mt = 0; mt < 3; mt++)
                #pragma unroll
                for (int nt = 0; nt < 3; nt++) {
                    mma_bf16(acc[mt][nt], ah[mt], bh[nt]);
                    mma_bf16(acc[mt][nt], ah[mt], bl[nt]);
                    mma_bf16(acc[mt][nt], al[mt], bh[nt]);
                }
        }
        __syncthreads();
    }

    #pragma unroll
    for (int mt = 0; mt < 3; mt++) {
        #pragma unroll
        for (int nt = 0; nt < 3; nt++) {
            int c0 = wm*48 + mt*16 + (lane >> 2);
            int d0 = wn*24 + nt*8 + (lane & 3)*2;
            #pragma unroll
            for (int half = 0; half < 2; half++) {
                int c = c0 + half*8;
                S[(((size_t)b*CH + d0  )*CH + c)*9 + kk] = acc[mt][nt][half*2 + 0];
                S[(((size_t)b*CH + d0+1)*CH + c)*9 + kk] = acc[mt][nt][half*2 + 1];
            }
        }
    }
}

// ---------------------------------------------------------------------------
// softmax over 864 -> Sn hi/lo with K order tap*96+c
// ---------------------------------------------------------------------------
__global__ __launch_bounds__(256)
void softmax_kernel(const float* __restrict__ S,
                    bf16* __restrict__ Sh, bf16* __restrict__ Sl)
{
    const int r = blockIdx.x;
    const int b = r / CH, d = r - b*CH;
    const float* row = S + (size_t)r * KTOT;
    const int tid = threadIdx.x;
    const float scale = 1.0f / 29.393876913398138f;   // 1/sqrt(864)

    float vals[4];
    int cnt = 0;
    float m = -1e30f;
    for (int i = tid; i < KTOT; i += 256) {
        float v = row[i] * scale;
        vals[cnt++] = v;
        m = fmaxf(m, v);
    }
    __shared__ float redm[8], reds[8];
    #pragma unroll
    for (int o = 16; o; o >>= 1) m = fmaxf(m, __shfl_xor_sync(0xffffffffu, m, o));
    if ((tid & 31) == 0) redm[tid >> 5] = m;
    __syncthreads();
    float bm = redm[0];
    #pragma unroll
    for (int w = 1; w < 8; w++) bm = fmaxf(bm, redm[w]);

    float s = 0.f;
    for (int c = 0; c < cnt; c++) { vals[c] = expf(vals[c] - bm); s += vals[c]; }
    #pragma unroll
    for (int o = 16; o; o >>= 1) s += __shfl_xor_sync(0xffffffffu, s, o);
    if ((tid & 31) == 0) reds[tid >> 5] = s;
    __syncthreads();
    float bs = 0.f;
    #pragma unroll
    for (int w = 0; w < 8; w++) bs += reds[w];
    float inv = 1.0f / bs;

    size_t obase = ((size_t)b*CH + d) * KTOT;
    cnt = 0;
    for (int i = tid; i < KTOT; i += 256) {
        float v = vals[cnt++] * inv;
        int c = i / 9, tap = i - c*9;
        bf16 hi = __float2bfloat16(v);
        size_t o = obase + tap*CH + c;
        Sh[o] = hi;
        Sl[o] = __float2bfloat16(v - __bfloat162float(hi));
    }
}

// ---------------------------------------------------------------------------
extern "C" void kernel_launch(void* const* d_in, const int* in_sizes, int n_in,
                              void* d_out, int out_size)
{
    const float* x  = (const float*)d_in[0];
    const float* W1 = (const float*)d_in[1];
    const float* W2 = (const float*)d_in[2];
    const float* W3 = (const float*)d_in[3];
    float* out = (float*)d_out;

    bf16 *xTh, *xTl, *Wh, *Wl, *Snh, *Snl, *u1h, *u1l, *u2h, *u2l;
    float *u1, *u2, *y3, *S;
    cudaGetSymbolAddress((void**)&xTh, g_xTh); cudaGetSymbolAddress((void**)&xTl, g_xTl);
    cudaGetSymbolAddress((void**)&Wh,  g_Wh);  cudaGetSymbolAddress((void**)&Wl,  g_Wl);
    cudaGetSymbolAddress((void**)&Snh, g_Snh); cudaGetSymbolAddress((void**)&Snl, g_Snl);
    cudaGetSymbolAddress((void**)&u1,  g_u1);  cudaGetSymbolAddress((void**)&u2,  g_u2);
    cudaGetSymbolAddress((void**)&u1h, g_u1h); cudaGetSymbolAddress((void**)&u1l, g_u1l);
    cudaGetSymbolAddress((void**)&u2h, g_u2h); cudaGetSymbolAddress((void**)&u2l, g_u2l);
    cudaGetSymbolAddress((void**)&y3,  g_y3);  cudaGetSymbolAddress((void**)&S,   g_S);

    const int smemC = 3*(2*NTILE*ROWB + 2*96*ROWB);   // 107520 (3-stage, NCONV=1)
    const int smemA = 3*4*96*ROWA;                    // 165888
    cudaFuncSetAttribute(gemm_conv1<0>, cudaFuncAttributeMaxDynamicSharedMemorySize, smemC);
    cudaFuncSetAttribute(gemm_conv1<1>, cudaFuncAttributeMaxDynamicSharedMemorySize, smemC);
    cudaFuncSetAttribute(attn_mma_kernel, cudaFuncAttributeMaxDynamicSharedMemorySize, smemA);

    prep_w_kernel<<<(3*CH*KTOT + 255)/256, 256>>>(W1, W2, W3);
    prepT_kernel<<<dim3(IMG, NB), 256>>>(x, xTh, xTl);

    dim3 gg(TILES_PER_B, NB);
    // conv1, conv2 -> unfold f32; conv3 -> NCHW f32  (2 CTAs/SM each)
    gemm_conv1<0><<<gg, 256, smemC>>>(xTh, xTl, Wh, Wl, 0, u1);
    gemm_conv1<0><<<gg, 256, smemC>>>(xTh, xTl, Wh + (size_t)CH*KTOT, Wl + (size_t)CH*KTOT, 0, u2);
    gemm_conv1<1><<<gg, 256, smemC>>>(xTh, xTl, Wh + (size_t)2*CH*KTOT, Wl + (size_t)2*CH*KTOT, 0, y3);

    // f32 -> bf16 hi/lo for tensor-core attention
    const size_t n4 = (size_t)NB*CH*9*1024/4;
    convert_u_kernel<<<(unsigned)((n4 + 255)/256), 256>>>(u1, u2, u1h, u1l, u2h, u2l);

    attn_mma_kernel<<<dim3(9, NB), 256, smemA>>>(u1h, u1l, u2h, u2l, S);
    softmax_kernel<<<NB*CH, 256>>>(S, Snh, Snl);

    // y3 -> transposed padded (reuse xT buffers)
    prepT_kernel<<<dim3(IMG, NB), 256>>>(y3, xTh, xTl);
    // conv4: per-batch A = softmaxed attention
    gemm_conv1<1><<<gg, 256, smemC>>>(xTh, xTl, Snh, Snl, (long)CH*KTOT, out);
}

// round 16
// speedup vs baseline: 1.1538x; 1.1538x over previous
#include <cuda_runtime.h>
#include <cuda_fp16.h>
#include <cstdint>

#define IMG 96
#define CH 96
#define NB 16
#define NPIX (IMG*IMG)           // 9216
#define PPIX (98*98)             // 9604 padded pixels (1-halo)
#define KTOT 864                 // 9 taps * 96 ci = 27*32
#define NCHUNK 27                // K chunks of 32
#define NTILE 128                // pixels per GEMM tile
#define TILES_PER_B 72
#define ROWB 80                  // smem row stride bytes (64B data + 16B pad)
#define ROWA 144                 // attn smem row stride (128B data + 16B pad)

#define WSCALE   64.0f           // weights scaled by 64 (lo-plane stays fp16-normal)
#define INV_WS   (1.0f/64.0f)
#define ASCALE   256.0f          // attn weights scaled by 256
#define INV_AS   (1.0f/256.0f)

typedef __half h16;

// ---------------- device scratch (BSS => zero; halo rows never written => stay 0) ----
__device__ __align__(128) h16 g_xTh[(size_t)NB*PPIX*CH];   // transposed padded input hi (x, later y3)
__device__ __align__(128) h16 g_xTl[(size_t)NB*PPIX*CH];   // lo
__device__ __align__(128) h16 g_Wh[(size_t)3*CH*KTOT];     // weights*64, K order tap*96+ci
__device__ __align__(128) h16 g_Wl[(size_t)3*CH*KTOT];
__device__ __align__(128) h16 g_Snh[(size_t)NB*CH*KTOT];   // softmaxed attn weights*256 hi
__device__ __align__(128) h16 g_Snl[(size_t)NB*CH*KTOT];
__device__ float g_u1[(size_t)NB*CH*9*1024];   // unfolded conv1 out (f32)
__device__ float g_u2[(size_t)NB*CH*9*1024];   // unfolded conv2 out (f32)
__device__ __align__(128) h16 g_u1h[(size_t)NB*CH*9*1024]; // fp16 hi/lo copies for attn mma
__device__ __align__(128) h16 g_u1l[(size_t)NB*CH*9*1024];
__device__ __align__(128) h16 g_u2h[(size_t)NB*CH*9*1024];
__device__ __align__(128) h16 g_u2l[(size_t)NB*CH*9*1024];
__device__ float g_y3[(size_t)NB*CH*NPIX];     // conv3 out NCHW
__device__ float g_S [(size_t)NB*CH*KTOT];     // attn logits

// ---------------- helpers ----------------
__device__ __forceinline__ uint32_t smem_u32(const void* p) {
    uint32_t a;
    asm("{ .reg .u64 t; cvta.to.shared.u64 t, %1; cvt.u32.u64 %0, t; }" : "=r"(a) : "l"(p));
    return a;
}
__device__ __forceinline__ void cp_async16(uint32_t dst, const void* src) {
    asm volatile("cp.async.cg.shared.global [%0], [%1], 16;" :: "r"(dst), "l"(src));
}
__device__ __forceinline__ void cp_commit() { asm volatile("cp.async.commit_group;" ::: "memory"); }
template<int N>
__device__ __forceinline__ void cp_wait() { asm volatile("cp.async.wait_group %0;" :: "n"(N) : "memory"); }

__device__ __forceinline__ void ldsm_x4(uint32_t* r, uint32_t addr) {
    asm volatile("ldmatrix.sync.aligned.m8n8.x4.shared.b16 {%0,%1,%2,%3}, [%4];"
                 : "=r"(r[0]), "=r"(r[1]), "=r"(r[2]), "=r"(r[3]) : "r"(addr));
}
__device__ __forceinline__ void ldsm_x2(uint32_t* r, uint32_t addr) {
    asm volatile("ldmatrix.sync.aligned.m8n8.x2.shared.b16 {%0,%1}, [%2];"
                 : "=r"(r[0]), "=r"(r[1]) : "r"(addr));
}
__device__ __forceinline__ void mma_f16(float* d, const uint32_t* a, const uint32_t* b) {
    asm volatile("mma.sync.aligned.m16n8k16.row.col.f32.f16.f16.f32 "
                 "{%0,%1,%2,%3}, {%4,%5,%6,%7}, {%8,%9}, {%0,%1,%2,%3};"
                 : "+f"(d[0]), "+f"(d[1]), "+f"(d[2]), "+f"(d[3])
                 : "r"(a[0]), "r"(a[1]), "r"(a[2]), "r"(a[3]), "r"(b[0]), "r"(b[1]));
}
__device__ __forceinline__ uint32_t pack2h(h16 a, h16 b) {
    __half2 t = __halves2half2(a, b);
    return *reinterpret_cast<uint32_t*>(&t);
}

// ---------------------------------------------------------------------------
// prepT: src NCHW fp32 -> transposed padded [b][(h+1)*98+(w+1)][ci] fp16 hi/lo.
// ---------------------------------------------------------------------------
__global__ __launch_bounds__(256)
void prepT_kernel(const float* __restrict__ src,
                  h16* __restrict__ dhi, h16* __restrict__ dlo)
{
    __shared__ float s[CH][97];
    const int h = blockIdx.x, b = blockIdx.y, tid = threadIdx.x;

    for (int e = tid; e < CH*IMG; e += 256) {
        int ci = e / IMG, w = e - ci*IMG;
        s[ci][w] = src[(((size_t)b*CH + ci)*IMG + h)*IMG + w];
    }
    __syncthreads();

    for (int e = tid; e < IMG*12; e += 256) {
        int w = e / 12, seg = e - w*12;
        int ci0 = seg*8;
        uint32_t uh[4], ul[4];
        #pragma unroll
        for (int i2 = 0; i2 < 4; i2++) {
            float a = s[ci0 + i2*2][w], c2 = s[ci0 + i2*2 + 1][w];
            h16 ha = __float2half(a), hc = __float2half(c2);
            h16 la = __float2half(a - __half2float(ha));
            h16 lc = __float2half(c2 - __half2float(hc));
            uh[i2] = pack2h(ha, hc);
            ul[i2] = pack2h(la, lc);
        }
        size_t base = ((size_t)b*PPIX + (size_t)(h+1)*98 + (w+1))*CH + ci0;
        *reinterpret_cast<uint4*>(dhi + base) = make_uint4(uh[0],uh[1],uh[2],uh[3]);
        *reinterpret_cast<uint4*>(dlo + base) = make_uint4(ul[0],ul[1],ul[2],ul[3]);
    }
}

// ---------------------------------------------------------------------------
// prep_w: W*64 -> fp16 hi/lo, K order tap*96+ci
// ---------------------------------------------------------------------------
__global__ __launch_bounds__(256)
void prep_w_kernel(const float* __restrict__ W1, const float* __restrict__ W2,
                   const float* __restrict__ W3)
{
    int idx = blockIdx.x*256 + threadIdx.x;
    if (idx >= 3*CH*KTOT) return;
    int conv = idx / (CH*KTOT);
    int r = idx - conv*(CH*KTOT);
    int co = r / KTOT, k = r - co*KTOT;
    int tap = k / CH, ci = k - tap*CH;
    const float* W = (conv == 0) ? W1 : (conv == 1) ? W2 : W3;
    float v = W[((size_t)co*CH + ci)*9 + tap] * WSCALE;
    h16 hi = __float2half(v);
    g_Wh[idx] = hi;
    g_Wl[idx] = __float2half(v - __half2float(hi));
}

// ---------------------------------------------------------------------------
// convert_u: fp32 unfold buffers -> fp16 hi/lo (coalesced, vectorized)
// ---------------------------------------------------------------------------
__global__ __launch_bounds__(256)
void convert_u_kernel(const float* __restrict__ u1, const float* __restrict__ u2,
                      h16* __restrict__ u1h, h16* __restrict__ u1l,
                      h16* __restrict__ u2h, h16* __restrict__ u2l)
{
    const size_t n4 = (size_t)NB*CH*9*1024/4;
    size_t i = (size_t)blockIdx.x*256 + threadIdx.x;
    if (i >= n4) return;
    float4 a = reinterpret_cast<const float4*>(u1)[i];
    float4 b = reinterpret_cast<const float4*>(u2)[i];
    h16 h0=__float2half(a.x), h1=__float2half(a.y),
        h2=__float2half(a.z), h3=__float2half(a.w);
    reinterpret_cast<uint2*>(u1h)[i] = make_uint2(pack2h(h0,h1), pack2h(h2,h3));
    reinterpret_cast<uint2*>(u1l)[i] =
        make_uint2(pack2h(__float2half(a.x-__half2float(h0)),
                          __float2half(a.y-__half2float(h1))),
                   pack2h(__float2half(a.z-__half2float(h2)),
                          __float2half(a.w-__half2float(h3))));
    h16 g0=__float2half(b.x), g1=__float2half(b.y),
        g2=__float2half(b.z), g3=__float2half(b.w);
    reinterpret_cast<uint2*>(u2h)[i] = make_uint2(pack2h(g0,g1), pack2h(g2,g3));
    reinterpret_cast<uint2*>(u2l)[i] =
        make_uint2(pack2h(__float2half(b.x-__half2float(g0)),
                          __float2half(b.y-__half2float(g1))),
                   pack2h(__float2half(b.z-__half2float(g2)),
                          __float2half(b.w-__half2float(g3))));
}

// ---------------------------------------------------------------------------
// gemm_fused: conv1+conv2+conv3 sharing B. fp16 hi/lo mma.
// cv0, cv1: 3-term -> unfold f32 (u1,u2). cv2: 2-term (drop Ah*Bl) -> NCHW (y3).
// A = W*64; epilogue scales by 1/64. 3-stage cp.async pipeline.
// ---------------------------------------------------------------------------
__global__ __launch_bounds__(256, 1)
void gemm_fused(const h16* __restrict__ Bh_, const h16* __restrict__ Bl_,
                const h16* __restrict__ Ah_, const h16* __restrict__ Al_,
                float* __restrict__ o0, float* __restrict__ o1,
                float* __restrict__ o2)
{
    extern __shared__ __align__(1024) char smem[];
    constexpr int AOFF  = 2*NTILE*ROWB;          // 20480
    constexpr int ABUF  = 96*ROWB;               // 7680
    constexpr int STAGE = AOFF + 6*ABUF;         // 66560

    const int tid = threadIdx.x, wid = tid >> 5, lane = tid & 31;
    const int wm = wid & 1, wn = wid >> 1;
    const int ntile = blockIdx.x, b = blockIdx.y;
    const uint32_t sb = smem_u32(smem);

    const int r0 = tid >> 2, seg0 = tid & 3;
    const int q0 = ntile*NTILE + r0;
    const int pb0 = (q0/IMG)*98 + (q0 - (q0/IMG)*IMG);
    const int q1 = q0 + 64;
    const int pb1 = (q1/IMG)*98 + (q1 - (q1/IMG)*IMG);

    const h16* Bs[2] = { Bh_ + (size_t)b*PPIX*CH, Bl_ + (size_t)b*PPIX*CH };
    const h16* As[2] = { Ah_, Al_ };

    float acc[3][3][4][4];
    #pragma unroll
    for (int cv = 0; cv < 3; cv++)
        #pragma unroll
        for (int mt = 0; mt < 3; mt++)
            #pragma unroll
            for (int nt = 0; nt < 4; nt++)
                #pragma unroll
                for (int j = 0; j < 4; j++) acc[cv][mt][nt][j] = 0.f;

    auto load_chunk = [&](int chunk, int stage) {
        const int tap = chunk/3;
        const int ci0 = (chunk - tap*3)*32;
        const int dh = tap/3, dw = tap - dh*3;
        const int doff = dh*98 + dw;
        const int koff = tap*CH + ci0;
        const uint32_t base = sb + stage*STAGE;
        #pragma unroll
        for (int t = 0; t < 2; t++) {
            cp_async16(base + t*(NTILE*ROWB) + r0*ROWB + seg0*16,
                       Bs[t] + (size_t)(pb0 + doff)*CH + ci0 + seg0*8);
            cp_async16(base + t*(NTILE*ROWB) + (r0+64)*ROWB + seg0*16,
                       Bs[t] + (size_t)(pb1 + doff)*CH + ci0 + seg0*8);
        }
        #pragma unroll
        for (int t = 0; t < 3; t++) {
            #pragma unroll
            for (int hl = 0; hl < 2; hl++) {
                const h16* src = As[hl] + (size_t)t*CH*KTOT + koff;
                uint32_t abase = base + AOFF + (t*2 + hl)*ABUF;
                cp_async16(abase + r0*ROWB + seg0*16, src + (size_t)r0*KTOT + seg0*8);
                if (tid < 128)
                    cp_async16(abase + (r0+64)*ROWB + seg0*16,
                               src + (size_t)(r0+64)*KTOT + seg0*8);
            }
        }
        cp_commit();
    };

    load_chunk(0, 0);
    load_chunk(1, 1);

    for (int c = 0; c < NCHUNK; c++) {
        if (c + 2 < NCHUNK) { load_chunk(c+2, (c+2)%3); cp_wait<2>(); }
        else if (c + 1 < NCHUNK) { cp_wait<1>(); }
        else { cp_wait<0>(); }
        __syncthreads();

        const uint32_t base = sb + (c % 3)*STAGE;
        #pragma unroll
        for (int ks = 0; ks < 2; ks++) {
            uint32_t bh[4][2], bl[4][2];
            #pragma unroll
            for (int nt = 0; nt < 4; nt++) {
                int rr = lane & 7, ii = (lane >> 3) & 1;
                int nl = wn*32 + nt*8 + rr;
                uint32_t ad = base + nl*ROWB + (ks*2 + ii)*16;
                ldsm_x2(bh[nt], ad);
                ldsm_x2(bl[nt], ad + NTILE*ROWB);
            }
            #pragma unroll
            for (int cv = 0; cv < 3; cv++) {
                uint32_t ab = base + AOFF + cv*2*ABUF;
                uint32_t ah[3][4], al[3][4];
                #pragma unroll
                for (int mt = 0; mt < 3; mt++) {
                    int ii = lane >> 3, rr = lane & 7;
                    int ml = wm*48 + mt*16 + (ii & 1)*8 + rr;
                    uint32_t ad = ab + ml*ROWB + (ks*2 + (ii >> 1))*16;
                    ldsm_x4(ah[mt], ad);
                    ldsm_x4(al[mt], ad + ABUF);
                }
                #pragma unroll
                for (int mt = 0; mt < 3; mt++)
                    #pragma unroll
                    for (int nt = 0; nt < 4; nt++) {
                        mma_f16(acc[cv][mt][nt], ah[mt], bh[nt]);
                        if (cv < 2) mma_f16(acc[cv][mt][nt], ah[mt], bl[nt]);
                        mma_f16(acc[cv][mt][nt], al[mt], bh[nt]);
                    }
            }
        }
        __syncthreads();
    }

    // ---- epilogue (scale 1/64) ----
    #pragma unroll
    for (int cv = 0; cv < 3; cv++) {
        float* dst = (cv == 0) ? o0 : (cv == 1 ? o1 : o2);
        const bool unfold = (cv < 2);
        #pragma unroll
        for (int mt = 0; mt < 3; mt++) {
            #pragma unroll
            for (int nt = 0; nt < 4; nt++) {
                int co0 = wm*48 + mt*16 + (lane >> 2);
                int p0  = ntile*NTILE + wn*32 + nt*8 + (lane & 3)*2;
                #pragma unroll
                for (int half = 0; half < 2; half++) {
                    int co = co0 + half*8;
                    float v0 = acc[cv][mt][nt][half*2 + 0] * INV_WS;
                    float v1 = acc[cv][mt][nt][half*2 + 1] * INV_WS;
                    if (unfold) {
                        size_t obase = ((size_t)b*CH + co)*9*1024;
                        int h0 = p0 / IMG, w0 = p0 - h0*IMG;
                        dst[obase + (size_t)((h0%3)*3 + (w0%3))*1024 + (h0/3)*32 + (w0/3)] = v0;
                        int p1 = p0 + 1;
                        int h1 = p1 / IMG, w1 = p1 - h1*IMG;
                        dst[obase + (size_t)((h1%3)*3 + (w1%3))*1024 + (h1/3)*32 + (w1/3)] = v1;
                    } else {
                        size_t o = ((size_t)b*CH + co)*NPIX + p0;
                        dst[o]     = v0;
                        dst[o + 1] = v1;
                    }
                }
            }
        }
    }
}

// ---------------------------------------------------------------------------
// gemm_att (conv4): A = softmax*256 (hi/lo, per-batch), B = y3 hi ONLY.
// 2-term: Ah*Bh + Al*Bh. Epilogue scales 1/256. NCHW f32 out.
// ---------------------------------------------------------------------------
__global__ __launch_bounds__(256, 1)
void gemm_att(const h16* __restrict__ Bh_,
              const h16* __restrict__ Ah_, const h16* __restrict__ Al_,
              float* __restrict__ o0)
{
    extern __shared__ __align__(1024) char smem[];
    constexpr int AOFF  = NTILE*ROWB;            // 10240 (B hi only)
    constexpr int ABUF  = 96*ROWB;               // 7680
    constexpr int STAGE = AOFF + 2*ABUF;         // 25600

    const int tid = threadIdx.x, wid = tid >> 5, lane = tid & 31;
    const int wm = wid & 1, wn = wid >> 1;
    const int ntile = blockIdx.x, b = blockIdx.y;
    const uint32_t sb = smem_u32(smem);

    const int r0 = tid >> 2, seg0 = tid & 3;
    const int q0 = ntile*NTILE + r0;
    const int pb0 = (q0/IMG)*98 + (q0 - (q0/IMG)*IMG);
    const int q1 = q0 + 64;
    const int pb1 = (q1/IMG)*98 + (q1 - (q1/IMG)*IMG);

    const h16* Bsrc = Bh_ + (size_t)b*PPIX*CH;
    const h16* As[2] = { Ah_ + (size_t)b*CH*KTOT, Al_ + (size_t)b*CH*KTOT };

    float acc[3][4][4];
    #pragma unroll
    for (int mt = 0; mt < 3; mt++)
        #pragma unroll
        for (int nt = 0; nt < 4; nt++)
            #pragma unroll
            for (int j = 0; j < 4; j++) acc[mt][nt][j] = 0.f;

    auto load_chunk = [&](int chunk, int stage) {
        const int tap = chunk/3;
        const int ci0 = (chunk - tap*3)*32;
        const int dh = tap/3, dw = tap - dh*3;
        const int doff = dh*98 + dw;
        const int koff = tap*CH + ci0;
        const uint32_t base = sb + stage*STAGE;
        cp_async16(base + r0*ROWB + seg0*16,
                   Bsrc + (size_t)(pb0 + doff)*CH + ci0 + seg0*8);
        cp_async16(base + (r0+64)*ROWB + seg0*16,
                   Bsrc + (size_t)(pb1 + doff)*CH + ci0 + seg0*8);
        #pragma unroll
        for (int hl = 0; hl < 2; hl++) {
            const h16* src = As[hl] + koff;
            uint32_t abase = base + AOFF + hl*ABUF;
            cp_async16(abase + r0*ROWB + seg0*16, src + (size_t)r0*KTOT + seg0*8);
            if (tid < 128)
                cp_async16(abase + (r0+64)*ROWB + seg0*16,
                           src + (size_t)(r0+64)*KTOT + seg0*8);
        }
        cp_commit();
    };

    load_chunk(0, 0);
    load_chunk(1, 1);

    for (int c = 0; c < NCHUNK; c++) {
        if (c + 2 < NCHUNK) { load_chunk(c+2, (c+2)%3); cp_wait<2>(); }
        else if (c + 1 < NCHUNK) { cp_wait<1>(); }
        else { cp_wait<0>(); }
        __syncthreads();

        const uint32_t base = sb + (c % 3)*STAGE;
        #pragma unroll
        for (int ks = 0; ks < 2; ks++) {
            uint32_t bh[4][2];
            #pragma unroll
            for (int nt = 0; nt < 4; nt++) {
                int rr = lane & 7, ii = (lane >> 3) & 1;
                int nl = wn*32 + nt*8 + rr;
                ldsm_x2(bh[nt], base + nl*ROWB + (ks*2 + ii)*16);
            }
            uint32_t ah[3][4], al[3][4];
            #pragma unroll
            for (int mt = 0; mt < 3; mt++) {
                int ii = lane >> 3, rr = lane & 7;
                int ml = wm*48 + mt*16 + (ii & 1)*8 + rr;
                uint32_t ad = base + AOFF + ml*ROWB + (ks*2 + (ii >> 1))*16;
                ldsm_x4(ah[mt], ad);
                ldsm_x4(al[mt], ad + ABUF);
            }
            #pragma unroll
            for (int mt = 0; mt < 3; mt++)
                #pragma unroll
                for (int nt = 0; nt < 4; nt++) {
                    mma_f16(acc[mt][nt], ah[mt], bh[nt]);
                    mma_f16(acc[mt][nt], al[mt], bh[nt]);
                }
        }
        __syncthreads();
    }

    #pragma unroll
    for (int mt = 0; mt < 3; mt++) {
        #pragma unroll
        for (int nt = 0; nt < 4; nt++) {
            int co0 = wm*48 + mt*16 + (lane >> 2);
            int p0  = ntile*NTILE + wn*32 + nt*8 + (lane & 3)*2;
            #pragma unroll
            for (int half = 0; half < 2; half++) {
                int co = co0 + half*8;
                size_t o = ((size_t)b*CH + co)*NPIX + p0;
                o0[o]     = acc[mt][nt][half*2 + 0] * INV_AS;
                o0[o + 1] = acc[mt][nt][half*2 + 1] * INV_AS;
            }
        }
    }
}

// ---------------------------------------------------------------------------
// attn_mma: S[b][d][c*9+k] = sum_l u1[b,c,k,l]*u2[b,d,k,l], 3-term fp16 mma.
// ---------------------------------------------------------------------------
__global__ __launch_bounds__(256, 1)
void attn_mma_kernel(const h16* __restrict__ u1h, const h16* __restrict__ u1l,
                     const h16* __restrict__ u2h, const h16* __restrict__ u2l,
                     float* __restrict__ S)
{
    extern __shared__ __align__(1024) char smem[];
    constexpr int TILE  = 96*ROWA;     // 13824
    constexpr int STG   = 4*TILE;      // 55296
    constexpr int NCH   = 16;

    const int kk = blockIdx.x, b = blockIdx.y;
    const int tid = threadIdx.x, wid = tid >> 5, lane = tid & 31;
    const int wm = wid & 1, wn = wid >> 1;
    const uint32_t sb = smem_u32(smem);

    const size_t rbase = ((size_t)b*CH*9 + kk)*1024;
    const h16* srcs[4] = { u1h + rbase, u1l + rbase, u2h + rbase, u2l + rbase };

    float acc[3][3][4];
    #pragma unroll
    for (int mt = 0; mt < 3; mt++)
        #pragma unroll
        for (int nt = 0; nt < 3; nt++)
            #pragma unroll
            for (int j = 0; j < 4; j++) acc[mt][nt][j] = 0.f;

    auto load_chunk = [&](int chunk, int stage) {
        const uint32_t base = sb + stage*STG;
        #pragma unroll
        for (int t = 0; t < 4; t++) {
            for (int e = tid; e < 96*8; e += 256) {
                int row = e >> 3, seg = e & 7;
                cp_async16(base + t*TILE + row*ROWA + seg*16,
                           srcs[t] + (size_t)row*9216 + chunk*64 + seg*8);
            }
        }
        cp_commit();
    };

    load_chunk(0, 0);
    load_chunk(1, 1);

    for (int c = 0; c < NCH; c++) {
        if (c + 2 < NCH) { load_chunk(c+2, (c+2)%3); cp_wait<2>(); }
        else if (c + 1 < NCH) { cp_wait<1>(); }
        else { cp_wait<0>(); }
        __syncthreads();

        const uint32_t base = sb + (c % 3)*STG;
        #pragma unroll
        for (int ks = 0; ks < 4; ks++) {
            uint32_t bh[3][2], bl[3][2];
            #pragma unroll
            for (int nt = 0; nt < 3; nt++) {
                int rr = lane & 7, ii = (lane >> 3) & 1;
                int nl = wn*24 + nt*8 + rr;
                uint32_t ad = base + 2*TILE + nl*ROWA + (ks*2 + ii)*16;
                ldsm_x2(bh[nt], ad);
                ldsm_x2(bl[nt], ad + TILE);
            }
            uint32_t ah[3][4], al[3][4];
            #pragma unroll
            for (int mt = 0; mt < 3; mt++) {
                int ii = lane >> 3, rr = lane & 7;
                int ml = wm*48 + mt*16 + (ii & 1)*8 + rr;
                uint32_t ad = base + ml*ROWA + (ks*2 + (ii >> 1))*16;
                ldsm_x4(ah[mt], ad);
                ldsm_x4(al[mt], ad + TILE);
            }
            #pragma unroll
            for (int mt = 0; mt < 3; mt++)
                #pragma unroll
                for (int nt = 0; nt < 3; nt++) {
                    mma_f16(acc[mt][nt], ah[mt], bh[nt]);
                    mma_f16(acc[mt][nt], ah[mt], bl[nt]);
                    mma_f16(acc[mt][nt], al[mt], bh[nt]);
                }
        }
        __syncthreads();
    }

    #pragma unroll
    for (int mt = 0; mt < 3; mt++) {
        #pragma unroll
        for (int nt = 0; nt < 3; nt++) {
            int c0 = wm*48 + mt*16 + (lane >> 2);
            int d0 = wn*24 + nt*8 + (lane & 3)*2;
            #pragma unroll
            for (int half = 0; half < 2; half++) {
                int c = c0 + half*8;
                S[(((size_t)b*CH + d0  )*CH + c)*9 + kk] = acc[mt][nt][half*2 + 0];
                S[(((size_t)b*CH + d0+1)*CH + c)*9 + kk] = acc[mt][nt][half*2 + 1];
            }
        }
    }
}

// ---------------------------------------------------------------------------
// softmax over 864 -> Sn (scaled by 256) fp16 hi/lo, K order tap*96+c
// ---------------------------------------------------------------------------
__global__ __launch_bounds__(256)
void softmax_kernel(const float* __restrict__ S,
                    h16* __restrict__ Sh, h16* __restrict__ Sl)
{
    const int r = blockIdx.x;
    const int b = r / CH, d = r - b*CH;
    const float* row = S + (size_t)r * KTOT;
    const int tid = threadIdx.x;
    const float scale = 1.0f / 29.393876913398138f;   // 1/sqrt(864)

    float vals[4];
    int cnt = 0;
    float m = -1e30f;
    for (int i = tid; i < KTOT; i += 256) {
        float v = row[i] * scale;
        vals[cnt++] = v;
        m = fmaxf(m, v);
    }
    __shared__ float redm[8], reds[8];
    #pragma unroll
    for (int o = 16; o; o >>= 1) m = fmaxf(m, __shfl_xor_sync(0xffffffffu, m, o));
    if ((tid & 31) == 0) redm[tid >> 5] = m;
    __syncthreads();
    float bm = redm[0];
    #pragma unroll
    for (int w = 1; w < 8; w++) bm = fmaxf(bm, redm[w]);

    float s = 0.f;
    for (int c = 0; c < cnt; c++) { vals[c] = expf(vals[c] - bm); s += vals[c]; }
    #pragma unroll
    for (int o = 16; o; o >>= 1) s += __shfl_xor_sync(0xffffffffu, s, o);
    if ((tid & 31) == 0) reds[tid >> 5] = s;
    __syncthreads();
    float bs = 0.f;
    #pragma unroll
    for (int w = 0; w < 8; w++) bs += reds[w];
    float inv = ASCALE / bs;

    size_t obase = ((size_t)b*CH + d) * KTOT;
    cnt = 0;
    for (int i = tid; i < KTOT; i += 256) {
        float v = vals[cnt++] * inv;
        int c = i / 9, tap = i - c*9;
        h16 hi = __float2half(v);
        size_t o = obase + tap*CH + c;
        Sh[o] = hi;
        Sl[o] = __float2half(v - __half2float(hi));
    }
}

// ---------------------------------------------------------------------------
extern "C" void kernel_launch(void* const* d_in, const int* in_sizes, int n_in,
                              void* d_out, int out_size)
{
    const float* x  = (const float*)d_in[0];
    const float* W1 = (const float*)d_in[1];
    const float* W2 = (const float*)d_in[2];
    const float* W3 = (const float*)d_in[3];
    float* out = (float*)d_out;

    h16 *xTh, *xTl, *Wh, *Wl, *Snh, *Snl, *u1h, *u1l, *u2h, *u2l;
    float *u1, *u2, *y3, *S;
    cudaGetSymbolAddress((void**)&xTh, g_xTh); cudaGetSymbolAddress((void**)&xTl, g_xTl);
    cudaGetSymbolAddress((void**)&Wh,  g_Wh);  cudaGetSymbolAddress((void**)&Wl,  g_Wl);
    cudaGetSymbolAddress((void**)&Snh, g_Snh); cudaGetSymbolAddress((void**)&Snl, g_Snl);
    cudaGetSymbolAddress((void**)&u1,  g_u1);  cudaGetSymbolAddress((void**)&u2,  g_u2);
    cudaGetSymbolAddress((void**)&u1h, g_u1h); cudaGetSymbolAddress((void**)&u1l, g_u1l);
    cudaGetSymbolAddress((void**)&u2h, g_u2h); cudaGetSymbolAddress((void**)&u2l, g_u2l);
    cudaGetSymbolAddress((void**)&y3,  g_y3);  cudaGetSymbolAddress((void**)&S,   g_S);

    const int smemF = 3*(2*NTILE*ROWB + 6*96*ROWB);   // 199680 (fused, 3 stages)
    const int smemC = 3*(NTILE*ROWB + 2*96*ROWB);     // 76800  (conv4, B hi only)
    const int smemA = 3*4*96*ROWA;                    // 165888
    cudaFuncSetAttribute(gemm_fused, cudaFuncAttributeMaxDynamicSharedMemorySize, smemF);
    cudaFuncSetAttribute(gemm_att,   cudaFuncAttributeMaxDynamicSharedMemorySize, smemC);
    cudaFuncSetAttribute(attn_mma_kernel, cudaFuncAttributeMaxDynamicSharedMemorySize, smemA);

    prep_w_kernel<<<(3*CH*KTOT + 255)/256, 256>>>(W1, W2, W3);
    prepT_kernel<<<dim3(IMG, NB), 256>>>(x, xTh, xTl);

    dim3 gg(TILES_PER_B, NB);
    // fused conv1+conv2+conv3 (cv2 2-term)
    gemm_fused<<<gg, 256, smemF>>>(xTh, xTl, Wh, Wl, u1, u2, y3);

    // f32 -> fp16 hi/lo for tensor-core attention
    const size_t n4 = (size_t)NB*CH*9*1024/4;
    convert_u_kernel<<<(unsigned)((n4 + 255)/256), 256>>>(u1, u2, u1h, u1l, u2h, u2l);

    attn_mma_kernel<<<dim3(9, NB), 256, smemA>>>(u1h, u1l, u2h, u2l, S);
    softmax_kernel<<<NB*CH, 256>>>(S, Snh, Snl);

    // y3 -> transposed padded (reuse xT buffers; conv4 uses hi only)
    prepT_kernel<<<dim3(IMG, NB), 256>>>(y3, xTh, xTl);
    // conv4: 2-term, B hi only
    gemm_att<<<gg, 256, smemC>>>(xTh, Snh, Snl, out);
}

// round 17
// speedup vs baseline: 1.2550x; 1.0877x over previous
#include <cuda_runtime.h>
#include <cuda_fp16.h>
#include <cstdint>

#define IMG 96
#define CH 96
#define NB 16
#define NPIX (IMG*IMG)           // 9216
#define PPIX (98*98)             // 9604 padded pixels (1-halo)
#define KTOT 864                 // 9 taps * 96 ci = 27*32
#define NCHUNK 27                // K chunks of 32
#define NTILE 128                // pixels per GEMM tile
#define TILES_PER_B 72
#define ROWB 80                  // smem row stride bytes (64B data + 16B pad)
#define ROWA 144                 // attn smem row stride (128B data + 16B pad)

#define WSCALE   64.0f           // weights scaled by 64 (lo-plane stays fp16-normal)
#define INV_WS   (1.0f/64.0f)
#define ASCALE   256.0f          // attn weights scaled by 256
#define INV_AS   (1.0f/256.0f)

typedef __half h16;

// ---------------- device scratch (BSS => zero; halo rows never written => stay 0) ----
__device__ __align__(128) h16 g_xTh[(size_t)NB*PPIX*CH];   // transposed padded input hi (x, later y3)
__device__ __align__(128) h16 g_xTl[(size_t)NB*PPIX*CH];   // lo
__device__ __align__(128) h16 g_Wh[(size_t)3*CH*KTOT];     // weights*64, K order tap*96+ci
__device__ __align__(128) h16 g_Wl[(size_t)3*CH*KTOT];
__device__ __align__(128) h16 g_Snh[(size_t)NB*CH*KTOT];   // softmaxed attn weights*256 hi
__device__ __align__(128) h16 g_Snl[(size_t)NB*CH*KTOT];
__device__ float g_u1[(size_t)NB*CH*9*1024];   // unfolded conv1 out (f32)
__device__ float g_u2[(size_t)NB*CH*9*1024];   // unfolded conv2 out (f32)
__device__ __align__(128) h16 g_u1h[(size_t)NB*CH*9*1024]; // fp16 hi/lo copies for attn mma
__device__ __align__(128) h16 g_u1l[(size_t)NB*CH*9*1024];
__device__ __align__(128) h16 g_u2h[(size_t)NB*CH*9*1024];
__device__ __align__(128) h16 g_u2l[(size_t)NB*CH*9*1024];
__device__ float g_y3[(size_t)NB*CH*NPIX];     // conv3 out NCHW
__device__ float g_S [(size_t)NB*CH*KTOT];     // attn logits

// ---------------- helpers ----------------
__device__ __forceinline__ uint32_t smem_u32(const void* p) {
    uint32_t a;
    asm("{ .reg .u64 t; cvta.to.shared.u64 t, %1; cvt.u32.u64 %0, t; }" : "=r"(a) : "l"(p));
    return a;
}
__device__ __forceinline__ void cp_async16(uint32_t dst, const void* src) {
    asm volatile("cp.async.cg.shared.global [%0], [%1], 16;" :: "r"(dst), "l"(src));
}
__device__ __forceinline__ void cp_commit() { asm volatile("cp.async.commit_group;" ::: "memory"); }
template<int N>
__device__ __forceinline__ void cp_wait() { asm volatile("cp.async.wait_group %0;" :: "n"(N) : "memory"); }

__device__ __forceinline__ void ldsm_x4(uint32_t* r, uint32_t addr) {
    asm volatile("ldmatrix.sync.aligned.m8n8.x4.shared.b16 {%0,%1,%2,%3}, [%4];"
                 : "=r"(r[0]), "=r"(r[1]), "=r"(r[2]), "=r"(r[3]) : "r"(addr));
}
__device__ __forceinline__ void ldsm_x2(uint32_t* r, uint32_t addr) {
    asm volatile("ldmatrix.sync.aligned.m8n8.x2.shared.b16 {%0,%1}, [%2];"
                 : "=r"(r[0]), "=r"(r[1]) : "r"(addr));
}
__device__ __forceinline__ void mma_f16(float* d, const uint32_t* a, const uint32_t* b) {
    asm volatile("mma.sync.aligned.m16n8k16.row.col.f32.f16.f16.f32 "
                 "{%0,%1,%2,%3}, {%4,%5,%6,%7}, {%8,%9}, {%0,%1,%2,%3};"
                 : "+f"(d[0]), "+f"(d[1]), "+f"(d[2]), "+f"(d[3])
                 : "r"(a[0]), "r"(a[1]), "r"(a[2]), "r"(a[3]), "r"(b[0]), "r"(b[1]));
}
__device__ __forceinline__ uint32_t pack2h(h16 a, h16 b) {
    __half2 t = __halves2half2(a, b);
    return *reinterpret_cast<uint32_t*>(&t);
}

// ---------------------------------------------------------------------------
// prepT: src NCHW fp32 -> transposed padded [b][(h+1)*98+(w+1)][ci] fp16 hi(/lo).
// WRITE_LO=0 skips the lo plane (v-path needs hi only).
// ---------------------------------------------------------------------------
template<int WRITE_LO>
__global__ __launch_bounds__(256)
void prepT_kernel(const float* __restrict__ src,
                  h16* __restrict__ dhi, h16* __restrict__ dlo)
{
    __shared__ float s[CH][97];
    const int h = blockIdx.x, b = blockIdx.y, tid = threadIdx.x;

    for (int e = tid; e < CH*IMG; e += 256) {
        int ci = e / IMG, w = e - ci*IMG;
        s[ci][w] = src[(((size_t)b*CH + ci)*IMG + h)*IMG + w];
    }
    __syncthreads();

    for (int e = tid; e < IMG*12; e += 256) {
        int w = e / 12, seg = e - w*12;
        int ci0 = seg*8;
        uint32_t uh[4], ul[4];
        #pragma unroll
        for (int i2 = 0; i2 < 4; i2++) {
            float a = s[ci0 + i2*2][w], c2 = s[ci0 + i2*2 + 1][w];
            h16 ha = __float2half(a), hc = __float2half(c2);
            uh[i2] = pack2h(ha, hc);
            if (WRITE_LO) {
                h16 la = __float2half(a - __half2float(ha));
                h16 lc = __float2half(c2 - __half2float(hc));
                ul[i2] = pack2h(la, lc);
            }
        }
        size_t base = ((size_t)b*PPIX + (size_t)(h+1)*98 + (w+1))*CH + ci0;
        *reinterpret_cast<uint4*>(dhi + base) = make_uint4(uh[0],uh[1],uh[2],uh[3]);
        if (WRITE_LO)
            *reinterpret_cast<uint4*>(dlo + base) = make_uint4(ul[0],ul[1],ul[2],ul[3]);
    }
}

// ---------------------------------------------------------------------------
// prep_w: W*64 -> fp16 hi/lo, K order tap*96+ci
// ---------------------------------------------------------------------------
__global__ __launch_bounds__(256)
void prep_w_kernel(const float* __restrict__ W1, const float* __restrict__ W2,
                   const float* __restrict__ W3)
{
    int idx = blockIdx.x*256 + threadIdx.x;
    if (idx >= 3*CH*KTOT) return;
    int conv = idx / (CH*KTOT);
    int r = idx - conv*(CH*KTOT);
    int co = r / KTOT, k = r - co*KTOT;
    int tap = k / CH, ci = k - tap*CH;
    const float* W = (conv == 0) ? W1 : (conv == 1) ? W2 : W3;
    float v = W[((size_t)co*CH + ci)*9 + tap] * WSCALE;
    h16 hi = __float2half(v);
    g_Wh[idx] = hi;
    g_Wl[idx] = __float2half(v - __half2float(hi));
}

// ---------------------------------------------------------------------------
// convert_u: fp32 unfold buffers -> fp16 hi/lo (coalesced, vectorized)
// ---------------------------------------------------------------------------
__global__ __launch_bounds__(256)
void convert_u_kernel(const float* __restrict__ u1, const float* __restrict__ u2,
                      h16* __restrict__ u1h, h16* __restrict__ u1l,
                      h16* __restrict__ u2h, h16* __restrict__ u2l)
{
    const size_t n4 = (size_t)NB*CH*9*1024/4;
    size_t i = (size_t)blockIdx.x*256 + threadIdx.x;
    if (i >= n4) return;
    float4 a = reinterpret_cast<const float4*>(u1)[i];
    float4 b = reinterpret_cast<const float4*>(u2)[i];
    h16 h0=__float2half(a.x), h1=__float2half(a.y),
        h2=__float2half(a.z), h3=__float2half(a.w);
    reinterpret_cast<uint2*>(u1h)[i] = make_uint2(pack2h(h0,h1), pack2h(h2,h3));
    reinterpret_cast<uint2*>(u1l)[i] =
        make_uint2(pack2h(__float2half(a.x-__half2float(h0)),
                          __float2half(a.y-__half2float(h1))),
                   pack2h(__float2half(a.z-__half2float(h2)),
                          __float2half(a.w-__half2float(h3))));
    h16 g0=__float2half(b.x), g1=__float2half(b.y),
        g2=__float2half(b.z), g3=__float2half(b.w);
    reinterpret_cast<uint2*>(u2h)[i] = make_uint2(pack2h(g0,g1), pack2h(g2,g3));
    reinterpret_cast<uint2*>(u2l)[i] =
        make_uint2(pack2h(__float2half(b.x-__half2float(g0)),
                          __float2half(b.y-__half2float(g1))),
                   pack2h(__float2half(b.z-__half2float(g2)),
                          __float2half(b.w-__half2float(g3))));
}

// ---------------------------------------------------------------------------
// gemm_fused: conv1+conv2+conv3 sharing B. fp16 hi/lo mma.
// cv0, cv1: 3-term -> unfold f32 (u1,u2). cv2: 2-term (drop Ah*Bl) -> NCHW (y3).
// A = W*64; epilogue scales by 1/64. 3-stage cp.async pipeline.
// ---------------------------------------------------------------------------
__global__ __launch_bounds__(256, 1)
void gemm_fused(const h16* __restrict__ Bh_, const h16* __restrict__ Bl_,
                const h16* __restrict__ Ah_, const h16* __restrict__ Al_,
                float* __restrict__ o0, float* __restrict__ o1,
                float* __restrict__ o2)
{
    extern __shared__ __align__(1024) char smem[];
    constexpr int AOFF  = 2*NTILE*ROWB;          // 20480
    constexpr int ABUF  = 96*ROWB;               // 7680
    constexpr int STAGE = AOFF + 6*ABUF;         // 66560

    const int tid = threadIdx.x, wid = tid >> 5, lane = tid & 31;
    const int wm = wid & 1, wn = wid >> 1;
    const int ntile = blockIdx.x, b = blockIdx.y;
    const uint32_t sb = smem_u32(smem);

    const int r0 = tid >> 2, seg0 = tid & 3;
    const int q0 = ntile*NTILE + r0;
    const int pb0 = (q0/IMG)*98 + (q0 - (q0/IMG)*IMG);
    const int q1 = q0 + 64;
    const int pb1 = (q1/IMG)*98 + (q1 - (q1/IMG)*IMG);

    const h16* Bs[2] = { Bh_ + (size_t)b*PPIX*CH, Bl_ + (size_t)b*PPIX*CH };
    const h16* As[2] = { Ah_, Al_ };

    float acc[3][3][4][4];
    #pragma unroll
    for (int cv = 0; cv < 3; cv++)
        #pragma unroll
        for (int mt = 0; mt < 3; mt++)
            #pragma unroll
            for (int nt = 0; nt < 4; nt++)
                #pragma unroll
                for (int j = 0; j < 4; j++) acc[cv][mt][nt][j] = 0.f;

    auto load_chunk = [&](int chunk, int stage) {
        const int tap = chunk/3;
        const int ci0 = (chunk - tap*3)*32;
        const int dh = tap/3, dw = tap - dh*3;
        const int doff = dh*98 + dw;
        const int koff = tap*CH + ci0;
        const uint32_t base = sb + stage*STAGE;
        #pragma unroll
        for (int t = 0; t < 2; t++) {
            cp_async16(base + t*(NTILE*ROWB) + r0*ROWB + seg0*16,
                       Bs[t] + (size_t)(pb0 + doff)*CH + ci0 + seg0*8);
            cp_async16(base + t*(NTILE*ROWB) + (r0+64)*ROWB + seg0*16,
                       Bs[t] + (size_t)(pb1 + doff)*CH + ci0 + seg0*8);
        }
        #pragma unroll
        for (int t = 0; t < 3; t++) {
            #pragma unroll
            for (int hl = 0; hl < 2; hl++) {
                const h16* src = As[hl] + (size_t)t*CH*KTOT + koff;
                uint32_t abase = base + AOFF + (t*2 + hl)*ABUF;
                cp_async16(abase + r0*ROWB + seg0*16, src + (size_t)r0*KTOT + seg0*8);
                if (tid < 128)
                    cp_async16(abase + (r0+64)*ROWB + seg0*16,
                               src + (size_t)(r0+64)*KTOT + seg0*8);
            }
        }
        cp_commit();
    };

    load_chunk(0, 0);
    load_chunk(1, 1);

    for (int c = 0; c < NCHUNK; c++) {
        if (c + 2 < NCHUNK) { load_chunk(c+2, (c+2)%3); cp_wait<2>(); }
        else if (c + 1 < NCHUNK) { cp_wait<1>(); }
        else { cp_wait<0>(); }
        __syncthreads();

        const uint32_t base = sb + (c % 3)*STAGE;
        #pragma unroll
        for (int ks = 0; ks < 2; ks++) {
            uint32_t bh[4][2], bl[4][2];
            #pragma unroll
            for (int nt = 0; nt < 4; nt++) {
                int rr = lane & 7, ii = (lane >> 3) & 1;
                int nl = wn*32 + nt*8 + rr;
                uint32_t ad = base + nl*ROWB + (ks*2 + ii)*16;
                ldsm_x2(bh[nt], ad);
                ldsm_x2(bl[nt], ad + NTILE*ROWB);
            }
            #pragma unroll
            for (int cv = 0; cv < 3; cv++) {
                uint32_t ab = base + AOFF + cv*2*ABUF;
                uint32_t ah[3][4], al[3][4];
                #pragma unroll
                for (int mt = 0; mt < 3; mt++) {
                    int ii = lane >> 3, rr = lane & 7;
                    int ml = wm*48 + mt*16 + (ii & 1)*8 + rr;
                    uint32_t ad = ab + ml*ROWB + (ks*2 + (ii >> 1))*16;
                    ldsm_x4(ah[mt], ad);
                    ldsm_x4(al[mt], ad + ABUF);
                }
                #pragma unroll
                for (int mt = 0; mt < 3; mt++)
                    #pragma unroll
                    for (int nt = 0; nt < 4; nt++) {
                        mma_f16(acc[cv][mt][nt], ah[mt], bh[nt]);
                        if (cv < 2) mma_f16(acc[cv][mt][nt], ah[mt], bl[nt]);
                        mma_f16(acc[cv][mt][nt], al[mt], bh[nt]);
                    }
            }
        }
        __syncthreads();
    }

    // ---- epilogue (scale 1/64) ----
    #pragma unroll
    for (int cv = 0; cv < 3; cv++) {
        float* dst = (cv == 0) ? o0 : (cv == 1 ? o1 : o2);
        const bool unfold = (cv < 2);
        #pragma unroll
        for (int mt = 0; mt < 3; mt++) {
            #pragma unroll
            for (int nt = 0; nt < 4; nt++) {
                int co0 = wm*48 + mt*16 + (lane >> 2);
                int p0  = ntile*NTILE + wn*32 + nt*8 + (lane & 3)*2;
                #pragma unroll
                for (int half = 0; half < 2; half++) {
                    int co = co0 + half*8;
                    float v0 = acc[cv][mt][nt][half*2 + 0] * INV_WS;
                    float v1 = acc[cv][mt][nt][half*2 + 1] * INV_WS;
                    if (unfold) {
                        size_t obase = ((size_t)b*CH + co)*9*1024;
                        int h0 = p0 / IMG, w0 = p0 - h0*IMG;
                        dst[obase + (size_t)((h0%3)*3 + (w0%3))*1024 + (h0/3)*32 + (w0/3)] = v0;
                        int p1 = p0 + 1;
                        int h1 = p1 / IMG, w1 = p1 - h1*IMG;
                        dst[obase + (size_t)((h1%3)*3 + (w1%3))*1024 + (h1/3)*32 + (w1/3)] = v1;
                    } else {
                        size_t o = ((size_t)b*CH + co)*NPIX + p0;
                        dst[o]     = v0;
                        dst[o + 1] = v1;
                    }
                }
            }
        }
    }
}

// ---------------------------------------------------------------------------
// gemm_att (conv4): A = softmax*256 hi ONLY (per-batch), B = y3 hi ONLY.
// 1-term: Ah*Bh. Epilogue scales 1/256. NCHW f32 out.
// ---------------------------------------------------------------------------
__global__ __launch_bounds__(256, 1)
void gemm_att(const h16* __restrict__ Bh_,
              const h16* __restrict__ Ah_,
              float* __restrict__ o0)
{
    extern __shared__ __align__(1024) char smem[];
    constexpr int AOFF  = NTILE*ROWB;            // 10240 (B hi only)
    constexpr int ABUF  = 96*ROWB;               // 7680  (A hi only)
    constexpr int STAGE = AOFF + ABUF;           // 17920

    const int tid = threadIdx.x, wid = tid >> 5, lane = tid & 31;
    const int wm = wid & 1, wn = wid >> 1;
    const int ntile = blockIdx.x, b = blockIdx.y;
    const uint32_t sb = smem_u32(smem);

    const int r0 = tid >> 2, seg0 = tid & 3;
    const int q0 = ntile*NTILE + r0;
    const int pb0 = (q0/IMG)*98 + (q0 - (q0/IMG)*IMG);
    const int q1 = q0 + 64;
    const int pb1 = (q1/IMG)*98 + (q1 - (q1/IMG)*IMG);

    const h16* Bsrc = Bh_ + (size_t)b*PPIX*CH;
    const h16* Asrc = Ah_ + (size_t)b*CH*KTOT;

    float acc[3][4][4];
    #pragma unroll
    for (int mt = 0; mt < 3; mt++)
        #pragma unroll
        for (int nt = 0; nt < 4; nt++)
            #pragma unroll
            for (int j = 0; j < 4; j++) acc[mt][nt][j] = 0.f;

    auto load_chunk = [&](int chunk, int stage) {
        const int tap = chunk/3;
        const int ci0 = (chunk - tap*3)*32;
        const int dh = tap/3, dw = tap - dh*3;
        const int doff = dh*98 + dw;
        const int koff = tap*CH + ci0;
        const uint32_t base = sb + stage*STAGE;
        cp_async16(base + r0*ROWB + seg0*16,
                   Bsrc + (size_t)(pb0 + doff)*CH + ci0 + seg0*8);
        cp_async16(base + (r0+64)*ROWB + seg0*16,
                   Bsrc + (size_t)(pb1 + doff)*CH + ci0 + seg0*8);
        {
            const h16* src = Asrc + koff;
            uint32_t abase = base + AOFF;
            cp_async16(abase + r0*ROWB + seg0*16, src + (size_t)r0*KTOT + seg0*8);
            if (tid < 128)
                cp_async16(abase + (r0+64)*ROWB + seg0*16,
                           src + (size_t)(r0+64)*KTOT + seg0*8);
        }
        cp_commit();
    };

    load_chunk(0, 0);
    load_chunk(1, 1);

    for (int c = 0; c < NCHUNK; c++) {
        if (c + 2 < NCHUNK) { load_chunk(c+2, (c+2)%3); cp_wait<2>(); }
        else if (c + 1 < NCHUNK) { cp_wait<1>(); }
        else { cp_wait<0>(); }
        __syncthreads();

        const uint32_t base = sb + (c % 3)*STAGE;
        #pragma unroll
        for (int ks = 0; ks < 2; ks++) {
            uint32_t bh[4][2];
            #pragma unroll
            for (int nt = 0; nt < 4; nt++) {
                int rr = lane & 7, ii = (lane >> 3) & 1;
                int nl = wn*32 + nt*8 + rr;
                ldsm_x2(bh[nt], base + nl*ROWB + (ks*2 + ii)*16);
            }
            uint32_t ah[3][4];
            #pragma unroll
            for (int mt = 0; mt < 3; mt++) {
                int ii = lane >> 3, rr = lane & 7;
                int ml = wm*48 + mt*16 + (ii & 1)*8 + rr;
                ldsm_x4(ah[mt], base + AOFF + ml*ROWB + (ks*2 + (ii >> 1))*16);
            }
            #pragma unroll
            for (int mt = 0; mt < 3; mt++)
                #pragma unroll
                for (int nt = 0; nt < 4; nt++)
                    mma_f16(acc[mt][nt], ah[mt], bh[nt]);
        }
        __syncthreads();
    }

    #pragma unroll
    for (int mt = 0; mt < 3; mt++) {
        #pragma unroll
        for (int nt = 0; nt < 4; nt++) {
            int co0 = wm*48 + mt*16 + (lane >> 2);
            int p0  = ntile*NTILE + wn*32 + nt*8 + (lane & 3)*2;
            #pragma unroll
            for (int half = 0; half < 2; half++) {
                int co = co0 + half*8;
                size_t o = ((size_t)b*CH + co)*NPIX + p0;
                o0[o]     = acc[mt][nt][half*2 + 0] * INV_AS;
                o0[o + 1] = acc[mt][nt][half*2 + 1] * INV_AS;
            }
        }
    }
}

// ---------------------------------------------------------------------------
// attn_mma: S[b][d][c*9+k] = sum_l u1[b,c,k,l]*u2[b,d,k,l], 3-term fp16 mma.
// ---------------------------------------------------------------------------
__global__ __launch_bounds__(256, 1)
void attn_mma_kernel(const h16* __restrict__ u1h, const h16* __restrict__ u1l,
                     const h16* __restrict__ u2h, const h16* __restrict__ u2l,
                     float* __restrict__ S)
{
    extern __shared__ __align__(1024) char smem[];
    constexpr int TILE  = 96*ROWA;     // 13824
    constexpr int STG   = 4*TILE;      // 55296
    constexpr int NCH   = 16;

    const int kk = blockIdx.x, b = blockIdx.y;
    const int tid = threadIdx.x, wid = tid >> 5, lane = tid & 31;
    const int wm = wid & 1, wn = wid >> 1;
    const uint32_t sb = smem_u32(smem);

    const size_t rbase = ((size_t)b*CH*9 + kk)*1024;
    const h16* srcs[4] = { u1h + rbase, u1l + rbase, u2h + rbase, u2l + rbase };

    float acc[3][3][4];
    #pragma unroll
    for (int mt = 0; mt < 3; mt++)
        #pragma unroll
        for (int nt = 0; nt < 3; nt++)
            #pragma unroll
            for (int j = 0; j < 4; j++) acc[mt][nt][j] = 0.f;

    auto load_chunk = [&](int chunk, int stage) {
        const uint32_t base = sb + stage*STG;
        #pragma unroll
        for (int t = 0; t < 4; t++) {
            for (int e = tid; e < 96*8; e += 256) {
                int row = e >> 3, seg = e & 7;
                cp_async16(base + t*TILE + row*ROWA + seg*16,
                           srcs[t] + (size_t)row*9216 + chunk*64 + seg*8);
            }
        }
        cp_commit();
    };

    load_chunk(0, 0);
    load_chunk(1, 1);

    for (int c = 0; c < NCH; c++) {
        if (c + 2 < NCH) { load_chunk(c+2, (c+2)%3); cp_wait<2>(); }
        else if (c + 1 < NCH) { cp_wait<1>(); }
        else { cp_wait<0>(); }
        __syncthreads();

        const uint32_t base = sb + (c % 3)*STG;
        #pragma unroll
        for (int ks = 0; ks < 4; ks++) {
            uint32_t bh[3][2], bl[3][2];
            #pragma unroll
            for (int nt = 0; nt < 3; nt++) {
                int rr = lane & 7, ii = (lane >> 3) & 1;
                int nl = wn*24 + nt*8 + rr;
                uint32_t ad = base + 2*TILE + nl*ROWA + (ks*2 + ii)*16;
                ldsm_x2(bh[nt], ad);
                ldsm_x2(bl[nt], ad + TILE);
            }
            uint32_t ah[3][4], al[3][4];
            #pragma unroll
            for (int mt = 0; mt < 3; mt++) {
                int ii = lane >> 3, rr = lane & 7;
                int ml = wm*48 + mt*16 + (ii & 1)*8 + rr;
                uint32_t ad = base + ml*ROWA + (ks*2 + (ii >> 1))*16;
                ldsm_x4(ah[mt], ad);
                ldsm_x4(al[mt], ad + TILE);
            }
            #pragma unroll
            for (int mt = 0; mt < 3; mt++)
                #pragma unroll
                for (int nt = 0; nt < 3; nt++) {
                    mma_f16(acc[mt][nt], ah[mt], bh[nt]);
                    mma_f16(acc[mt][nt], ah[mt], bl[nt]);
                    mma_f16(acc[mt][nt], al[mt], bh[nt]);
                }
        }
        __syncthreads();
    }

    #pragma unroll
    for (int mt = 0; mt < 3; mt++) {
        #pragma unroll
        for (int nt = 0; nt < 3; nt++) {
            int c0 = wm*48 + mt*16 + (lane >> 2);
            int d0 = wn*24 + nt*8 + (lane & 3)*2;
            #pragma unroll
            for (int half = 0; half < 2; half++) {
                int c = c0 + half*8;
                S[(((size_t)b*CH + d0  )*CH + c)*9 + kk] = acc[mt][nt][half*2 + 0];
                S[(((size_t)b*CH + d0+1)*CH + c)*9 + kk] = acc[mt][nt][half*2 + 1];
            }
        }
    }
}

// ---------------------------------------------------------------------------
// softmax over 864 -> Sn (scaled by 256) fp16 hi, K order tap*96+c
// ---------------------------------------------------------------------------
__global__ __launch_bounds__(256)
void softmax_kernel(const float* __restrict__ S,
                    h16* __restrict__ Sh)
{
    const int r = blockIdx.x;
    const int b = r / CH, d = r - b*CH;
    const float* row = S + (size_t)r * KTOT;
    const int tid = threadIdx.x;
    const float scale = 1.0f / 29.393876913398138f;   // 1/sqrt(864)

    float vals[4];
    int cnt = 0;
    float m = -1e30f;
    for (int i = tid; i < KTOT; i += 256) {
        float v = row[i] * scale;
        vals[cnt++] = v;
        m = fmaxf(m, v);
    }
    __shared__ float redm[8], reds[8];
    #pragma unroll
    for (int o = 16; o; o >>= 1) m = fmaxf(m, __shfl_xor_sync(0xffffffffu, m, o));
    if ((tid & 31) == 0) redm[tid >> 5] = m;
    __syncthreads();
    float bm = redm[0];
    #pragma unroll
    for (int w = 1; w < 8; w++) bm = fmaxf(bm, redm[w]);

    float s = 0.f;
    for (int c = 0; c < cnt; c++) { vals[c] = expf(vals[c] - bm); s += vals[c]; }
    #pragma unroll
    for (int o = 16; o; o >>= 1) s += __shfl_xor_sync(0xffffffffu, s, o);
    if ((tid & 31) == 0) reds[tid >> 5] = s;
    __syncthreads();
    float bs = 0.f;
    #pragma unroll
    for (int w = 0; w < 8; w++) bs += reds[w];
    float inv = ASCALE / bs;

    size_t obase = ((size_t)b*CH + d) * KTOT;
    cnt = 0;
    for (int i = tid; i < KTOT; i += 256) {
        float v = vals[cnt++] * inv;
        int c = i / 9, tap = i - c*9;
        Sh[obase + tap*CH + c] = __float2half(v);
    }
}

// ---------------------------------------------------------------------------
extern "C" void kernel_launch(void* const* d_in, const int* in_sizes, int n_in,
                              void* d_out, int out_size)
{
    const float* x  = (const float*)d_in[0];
    const float* W1 = (const float*)d_in[1];
    const float* W2 = (const float*)d_in[2];
    const float* W3 = (const float*)d_in[3];
    float* out = (float*)d_out;

    h16 *xTh, *xTl, *Wh, *Wl, *Snh, *u1h, *u1l, *u2h, *u2l;
    float *u1, *u2, *y3, *S;
    cudaGetSymbolAddress((void**)&xTh, g_xTh); cudaGetSymbolAddress((void**)&xTl, g_xTl);
    cudaGetSymbolAddress((void**)&Wh,  g_Wh);  cudaGetSymbolAddress((void**)&Wl,  g_Wl);
    cudaGetSymbolAddress((void**)&Snh, g_Snh);
    cudaGetSymbolAddress((void**)&u1,  g_u1);  cudaGetSymbolAddress((void**)&u2,  g_u2);
    cudaGetSymbolAddress((void**)&u1h, g_u1h); cudaGetSymbolAddress((void**)&u1l, g_u1l);
    cudaGetSymbolAddress((void**)&u2h, g_u2h); cudaGetSymbolAddress((void**)&u2l, g_u2l);
    cudaGetSymbolAddress((void**)&y3,  g_y3);  cudaGetSymbolAddress((void**)&S,   g_S);

    const int smemF = 3*(2*NTILE*ROWB + 6*96*ROWB);   // 199680 (fused, 3 stages)
    const int smemC = 3*(NTILE*ROWB + 96*ROWB);       // 53760  (conv4, hi-only A and B)
    const int smemA = 3*4*96*ROWA;                    // 165888
    cudaFuncSetAttribute(gemm_fused, cudaFuncAttributeMaxDynamicSharedMemorySize, smemF);
    cudaFuncSetAttribute(gemm_att,   cudaFuncAttributeMaxDynamicSharedMemorySize, smemC);
    cudaFuncSetAttribute(attn_mma_kernel, cudaFuncAttributeMaxDynamicSharedMemorySize, smemA);

    prep_w_kernel<<<(3*CH*KTOT + 255)/256, 256>>>(W1, W2, W3);
    prepT_kernel<1><<<dim3(IMG, NB), 256>>>(x, xTh, xTl);

    dim3 gg(TILES_PER_B, NB);
    // fused conv1+conv2+conv3 (cv2 2-term)
    gemm_fused<<<gg, 256, smemF>>>(xTh, xTl, Wh, Wl, u1, u2, y3);

    // f32 -> fp16 hi/lo for tensor-core attention
    const size_t n4 = (size_t)NB*CH*9*1024/4;
    convert_u_kernel<<<(unsigned)((n4 + 255)/256), 256>>>(u1, u2, u1h, u1l, u2h, u2l);

    attn_mma_kernel<<<dim3(9, NB), 256, smemA>>>(u1h, u1l, u2h, u2l, S);
    softmax_kernel<<<NB*CH, 256>>>(S, Snh);

    // y3 -> transposed padded, hi only (conv4 is 1-term)
    prepT_kernel<0><<<dim3(IMG, NB), 256>>>(y3, xTh, xTl);
    // conv4: 1-term Ah*Bh
    gemm_att<<<gg, 256, smemC>>>(xTh, Snh, out);
}